// round 2
// baseline (speedup 1.0000x reference)
#include <cuda_runtime.h>
#include <math.h>

// Problem dims
#define BCn   512            // B*C
#define Hn    256
#define Mn    32
#define NROW  (BCn*Hn)       // 131072 rows for stage-1 GEMM
#define NMODE (BCn*Mn*Mn)    // 524288

// Output packing offsets (tuple order, flattened+concatenated)
#define OFF_E    0
#define OFF_U    524288
#define OFF_EF   1048576
#define OFF_WI   1572864
#define OFF_US   2097152
#define OFF_ES   2098176
#define OFF_ERR  2099200
#define OFF_CAL  2623488

// Scratch (device globals: allocation-free rule)
__device__ float  g_Y[2][(size_t)NROW*64]; // stage-1 outputs: [pred/gt][row][j] j<32:Re(k2=j), j>=32:Im(k2=j-32)
__device__ float2 g_modes[NMODE];          // pred modes (re,im) for MLP
__device__ float  g_totE[BCn];
__device__ float  g_Bm[256*64];            // stage-1 DFT matrix  B[n2][j]
__device__ float  g_Am[64*256];            // stage-2 DFT matrix  A[i][n1] i<32:cos(k1=i), i>=32:sin(k1=i-32)

// ---------------------------------------------------------------------------
// K0: build DFT matrices. phase = (k*n) mod 256; exp(-i*2*pi*k*n/256)
// ---------------------------------------------------------------------------
__global__ void k_init() {
    int idx = blockIdx.x * 256 + threadIdx.x;   // 0 .. 32767
    if (idx < 256*64) {
        int n = idx >> 6, j = idx & 63;
        int k = j & 31;
        int p = (k * n) & 255;
        float s, c;
        sincospif((float)p * (1.0f/128.0f), &s, &c);  // angle = 2*pi*p/256
        g_Bm[idx] = (j < 32) ? c : -s;   // Re: +cos, Im: -sin
    } else if (idx < 2*256*64) {
        int t = idx - 256*64;
        int i = t >> 8, n = t & 255;
        int k = i & 31;
        int p = (k * n) & 255;
        float s, c;
        sincospif((float)p * (1.0f/128.0f), &s, &c);
        g_Am[t] = (i < 32) ? c : s;      // cos rows then sin rows (sign handled in combine)
    }
}

// ---------------------------------------------------------------------------
// K1: stage-1 GEMM  Y[131072 x 64] = X[131072 x 256] @ B[256 x 64]
// block: 256 thr, tile 128 rows x 64 cols, k-chunk 32, per-thread 8x4
// grid: (1024, 2)  y: 0=prediction, 1=ground_truth
// ---------------------------------------------------------------------------
__global__ __launch_bounds__(256) void k_dft1(const float* __restrict__ Xp,
                                              const float* __restrict__ Xg) {
    __shared__ float Xs[32][132];   // transposed: Xs[k][r]
    __shared__ float Bs[32][68];
    const float* X = (blockIdx.y == 0) ? Xp : Xg;
    float* Y = g_Y[blockIdx.y];
    const int R0 = blockIdx.x * 128;
    const int tid = threadIdx.x;
    const int ty = tid >> 4, tx = tid & 15;

    float acc[8][4];
    #pragma unroll
    for (int i = 0; i < 8; i++)
        #pragma unroll
        for (int j = 0; j < 4; j++) acc[i][j] = 0.f;

    for (int kk = 0; kk < 256; kk += 32) {
        #pragma unroll
        for (int u = 0; u < 4; u++) {
            int v = tid + u*256;            // 1024 float4 loads of X tile
            int r = v >> 3, c4 = v & 7;
            float4 xv = reinterpret_cast<const float4*>(X + (size_t)(R0 + r)*256 + kk)[c4];
            Xs[c4*4+0][r] = xv.x; Xs[c4*4+1][r] = xv.y;
            Xs[c4*4+2][r] = xv.z; Xs[c4*4+3][r] = xv.w;
        }
        #pragma unroll
        for (int u = 0; u < 2; u++) {
            int v = tid + u*256;            // 512 float4 loads of B tile
            int k = v >> 4, j4 = v & 15;
            float4 bv = reinterpret_cast<const float4*>(g_Bm + (size_t)(kk + k)*64)[j4];
            *reinterpret_cast<float4*>(&Bs[k][j4*4]) = bv;
        }
        __syncthreads();
        #pragma unroll 8
        for (int k = 0; k < 32; k++) {
            float a[8], b[4];
            #pragma unroll
            for (int i = 0; i < 8; i++) a[i] = Xs[k][ty*8 + i];
            #pragma unroll
            for (int j = 0; j < 4; j++) b[j] = Bs[k][tx*4 + j];
            #pragma unroll
            for (int i = 0; i < 8; i++)
                #pragma unroll
                for (int j = 0; j < 4; j++)
                    acc[i][j] = fmaf(a[i], b[j], acc[i][j]);
        }
        __syncthreads();
    }
    #pragma unroll
    for (int i = 0; i < 8; i++) {
        float4 o = make_float4(acc[i][0], acc[i][1], acc[i][2], acc[i][3]);
        *reinterpret_cast<float4*>(Y + (size_t)(R0 + ty*8 + i)*64 + tx*4) = o;
    }
}

// ---------------------------------------------------------------------------
// K2: stage-2 per (b,c):  P[64x64] = A[64x256] @ Y[256x64]  (pred & gt)
// epilogue: modes, energies, errors, per-bc total energy
// grid 512 blocks x 256 thr, per-thread 4x4 (x2 tensors)
// ---------------------------------------------------------------------------
__global__ __launch_bounds__(256) void k_stage2(float* __restrict__ out) {
    __shared__ float buf[2*64*68];   // union: {As,Yps,Ygs}[32][68] each  /  {Pp,Pg}[64][68]
    __shared__ float red[8];
    float* As  = buf;
    float* Yps = buf + 32*68;
    float* Ygs = buf + 2*32*68;
    float* Pp  = buf;
    float* Pg  = buf + 64*68;

    const int bc  = blockIdx.x;
    const int tid = threadIdx.x;
    const int ty = tid >> 4, tx = tid & 15;
    const float* Yp = g_Y[0] + (size_t)bc*256*64;
    const float* Yg = g_Y[1] + (size_t)bc*256*64;

    float ap[4][4], ag[4][4];
    #pragma unroll
    for (int i = 0; i < 4; i++)
        #pragma unroll
        for (int j = 0; j < 4; j++) { ap[i][j] = 0.f; ag[i][j] = 0.f; }

    for (int n0 = 0; n0 < 256; n0 += 32) {
        #pragma unroll
        for (int u = 0; u < 2; u++) {           // A transpose load: As[k][i] = A[i][n0+k]
            int v = tid + u*256;
            int i = v >> 3, c4 = v & 7;
            float4 av = reinterpret_cast<const float4*>(g_Am + (size_t)i*256 + n0)[c4];
            As[(c4*4+0)*68 + i] = av.x; As[(c4*4+1)*68 + i] = av.y;
            As[(c4*4+2)*68 + i] = av.z; As[(c4*4+3)*68 + i] = av.w;
        }
        #pragma unroll
        for (int u = 0; u < 2; u++) {
            int v = tid + u*256;
            int k = v >> 4, j4 = v & 15;
            *reinterpret_cast<float4*>(&Yps[k*68 + j4*4]) =
                reinterpret_cast<const float4*>(Yp + (size_t)(n0 + k)*64)[j4];
            *reinterpret_cast<float4*>(&Ygs[k*68 + j4*4]) =
                reinterpret_cast<const float4*>(Yg + (size_t)(n0 + k)*64)[j4];
        }
        __syncthreads();
        #pragma unroll 8
        for (int k = 0; k < 32; k++) {
            float a[4], bp[4], bg[4];
            #pragma unroll
            for (int i = 0; i < 4; i++) a[i]  = As [k*68 + ty*4 + i];
            #pragma unroll
            for (int j = 0; j < 4; j++) { bp[j] = Yps[k*68 + tx*4 + j];
                                          bg[j] = Ygs[k*68 + tx*4 + j]; }
            #pragma unroll
            for (int i = 0; i < 4; i++)
                #pragma unroll
                for (int j = 0; j < 4; j++) {
                    ap[i][j] = fmaf(a[i], bp[j], ap[i][j]);
                    ag[i][j] = fmaf(a[i], bg[j], ag[i][j]);
                }
        }
        __syncthreads();
    }
    #pragma unroll
    for (int i = 0; i < 4; i++) {
        *reinterpret_cast<float4*>(&Pp[(ty*4+i)*68 + tx*4]) =
            make_float4(ap[i][0], ap[i][1], ap[i][2], ap[i][3]);
        *reinterpret_cast<float4*>(&Pg[(ty*4+i)*68 + tx*4]) =
            make_float4(ag[i][0], ag[i][1], ag[i][2], ag[i][3]);
    }
    __syncthreads();

    float esum = 0.f;
    #pragma unroll
    for (int u = 0; u < 4; u++) {
        int p  = u*256 + tid;                // coalesced; k1 const per warp, k2 = lane
        int k1 = p >> 5, k2 = p & 31;
        float rp = Pp[k1*68 + k2]      + Pp[(32+k1)*68 + 32 + k2];
        float ip = Pp[k1*68 + 32 + k2] - Pp[(32+k1)*68 + k2];
        float rg = Pg[k1*68 + k2]      + Pg[(32+k1)*68 + 32 + k2];
        float ig = Pg[k1*68 + 32 + k2] - Pg[(32+k1)*68 + k2];
        float en = rp*rp + ip*ip;
        float dr = rp - rg, di = ip - ig;
        size_t gi = (size_t)bc*1024 + p;
        out[OFF_E   + gi] = en;
        out[OFF_ERR + gi] = dr*dr + di*di;
        g_modes[gi] = make_float2(rp, ip);
        esum += en;
    }
    #pragma unroll
    for (int o = 16; o > 0; o >>= 1) esum += __shfl_down_sync(0xffffffffu, esum, o);
    if ((tid & 31) == 0) red[tid >> 5] = esum;
    __syncthreads();
    if (tid == 0) {
        float s = 0.f;
        #pragma unroll
        for (int w = 0; w < 8; w++) s += red[w];
        g_totE[bc] = s;
    }
}

// ---------------------------------------------------------------------------
// K3: MLP per mode point: 2 -> 64 (relu) -> 32 (relu) -> 1 (softplus)
// block: 128 thr, 64 points; GEMM-structured through shared memory
// ---------------------------------------------------------------------------
__global__ __launch_bounds__(128) void k_mlp(const float* __restrict__ W1,
                                             const float* __restrict__ b1,
                                             const float* __restrict__ W2,
                                             const float* __restrict__ b2,
                                             const float* __restrict__ W3,
                                             const float* __restrict__ b3v,
                                             float* __restrict__ out) {
    __shared__ float  W1s[2][64];
    __shared__ float  b1s[64];
    __shared__ float  W2s[64][36];
    __shared__ float  b2s[32];
    __shared__ float  W3s[32];
    __shared__ float  b3s;
    __shared__ float2 Pts[64];
    __shared__ float  H1t[64][68];   // transposed: H1t[k][p]
    __shared__ float  H2s[64][36];   // H2s[p][c]

    const int tid  = threadIdx.x;
    const int base = blockIdx.x * 64;

    if (tid < 64) { W1s[0][tid] = W1[tid]; W1s[1][tid] = W1[64 + tid]; b1s[tid] = b1[tid]; }
    for (int v = tid; v < 2048; v += 128) W2s[v >> 5][v & 31] = W2[v];
    if (tid < 32) { b2s[tid] = b2[tid]; W3s[tid] = W3[tid]; }
    if (tid == 0) b3s = b3v[0];
    if (tid < 64) Pts[tid] = g_modes[base + tid];
    __syncthreads();

    { // layer 1: each thread does half a point's 64 outputs
        int p = tid >> 1, jb = (tid & 1) * 32;
        float2 x = Pts[p];
        #pragma unroll 8
        for (int j = 0; j < 32; j++) {
            int jj = jb + j;
            float h = fmaf(x.x, W1s[0][jj], fmaf(x.y, W1s[1][jj], b1s[jj]));
            H1t[jj][p] = fmaxf(h, 0.f);
        }
    }
    __syncthreads();

    { // layer 2: GEMM [64 pts x 32] with K=64, per-thread 4x4
        int ty = tid >> 3, tx = tid & 7;
        float acc[4][4];
        #pragma unroll
        for (int i = 0; i < 4; i++)
            #pragma unroll
            for (int j = 0; j < 4; j++) acc[i][j] = b2s[tx*4 + j];
        #pragma unroll 8
        for (int k = 0; k < 64; k++) {
            float a[4], b[4];
            #pragma unroll
            for (int i = 0; i < 4; i++) a[i] = H1t[k][ty*4 + i];
            #pragma unroll
            for (int j = 0; j < 4; j++) b[j] = W2s[k][tx*4 + j];
            #pragma unroll
            for (int i = 0; i < 4; i++)
                #pragma unroll
                for (int j = 0; j < 4; j++) acc[i][j] = fmaf(a[i], b[j], acc[i][j]);
        }
        #pragma unroll
        for (int i = 0; i < 4; i++)
            #pragma unroll
            for (int j = 0; j < 4; j++)
                H2s[ty*4 + i][tx*4 + j] = fmaxf(acc[i][j], 0.f);
    }
    __syncthreads();

    if (tid < 64) { // layer 3 + softplus
        float acc = b3s;
        #pragma unroll
        for (int c = 0; c < 32; c++) acc = fmaf(H2s[tid][c], W3s[c], acc);
        float sp = fmaxf(acc, 0.f) + log1pf(expf(-fabsf(acc)));
        out[OFF_U + base + tid] = sp;
    }
}

// ---------------------------------------------------------------------------
// K4: energy fractions + weighted importance (elementwise)
// ---------------------------------------------------------------------------
__global__ void k_frac(float* __restrict__ out) {
    int i = blockIdx.x * 256 + threadIdx.x;
    if (i >= NMODE) return;
    float tot = g_totE[i >> 10];
    float ef = out[OFF_E + i] / (tot + 1e-8f);
    out[OFF_EF + i] = ef;
    out[OFF_WI + i] = ef * out[OFF_U + i];
}

// ---------------------------------------------------------------------------
// K5: spectra means + Pearson calibration over the 512-sample batch axis
// one thread per mode, two-pass (matches reference's centered computation)
// ---------------------------------------------------------------------------
__global__ void k_stats(float* __restrict__ out) {
    int m = blockIdx.x * 256 + threadIdx.x;   // 0..1023
    const float* U  = out + OFF_U;
    const float* E  = out + OFF_E;
    const float* ER = out + OFF_ERR;
    float su = 0.f, se = 0.f, sr = 0.f;
    #pragma unroll 4
    for (int r = 0; r < 512; r++) {
        su += U [r*1024 + m];
        se += E [r*1024 + m];
        sr += ER[r*1024 + m];
    }
    float mu = su * (1.f/512.f), mr = sr * (1.f/512.f);
    out[OFF_US + m] = mu;
    out[OFF_ES + m] = se * (1.f/512.f);
    float num = 0.f, du = 0.f, de = 0.f;
    #pragma unroll 4
    for (int r = 0; r < 512; r++) {
        float uc = U [r*1024 + m] - mu;
        float ec = ER[r*1024 + m] - mr;
        num += uc*ec; du += uc*uc; de += ec*ec;
    }
    out[OFF_CAL + m] = num / (sqrtf(du * de) + 1e-8f);
}

// ---------------------------------------------------------------------------
extern "C" void kernel_launch(void* const* d_in, const int* in_sizes, int n_in,
                              void* d_out, int out_size) {
    const float* pred = (const float*)d_in[0];
    // d_in[1] (uncertainty) is unused by the reference math
    const float* gt   = (const float*)d_in[2];
    const float* W1   = (const float*)d_in[3];
    const float* b1   = (const float*)d_in[4];
    const float* W2   = (const float*)d_in[5];
    const float* b2   = (const float*)d_in[6];
    const float* W3   = (const float*)d_in[7];
    const float* b3   = (const float*)d_in[8];
    float* out = (float*)d_out;

    k_init  <<<128, 256>>>();
    k_dft1  <<<dim3(1024, 2), 256>>>(pred, gt);
    k_stage2<<<512, 256>>>(out);
    k_mlp   <<<NMODE/64, 128>>>(W1, b1, W2, b2, W3, b3, out);
    k_frac  <<<NMODE/256, 256>>>(out);
    k_stats <<<4, 256>>>(out);
}

// round 6
// speedup vs baseline: 1.5302x; 1.5302x over previous
#include <cuda_runtime.h>
#include <math.h>

// Problem dims
#define BCn   512            // B*C
#define NROW  (BCn*256)      // 131072 rows for stage-1 GEMM
#define NMODE (BCn*32*32)    // 524288

// Output packing offsets (tuple order, flattened+concatenated)
#define OFF_E    0
#define OFF_U    524288
#define OFF_EF   1048576
#define OFF_WI   1572864
#define OFF_US   2097152
#define OFF_ES   2098176
#define OFF_ERR  2099200
#define OFF_CAL  2623488

// Scratch (device globals: allocation-free rule)
// g_Y column layout j' (parity-permuted): g=j'>>4 (0=ReEven,1=ReOdd,2=ImEven,3=ImOdd),
// m=j'&15, k2 = 2m + (g&1).
__device__ float  g_Y[2][(size_t)NROW*64];
__device__ float2 g_modes[NMODE];
__device__ float  g_totE[BCn];
__device__ float  g_Bm2[128*64];   // stage-1 folded DFT matrix  B2[n][j']  n=0..127
__device__ float  g_Am2[64*128];   // stage-2 folded DFT matrix  A2[i'][n]  n=0..127

// ---------------------------------------------------------------------------
// K0: build folded DFT matrices.
// B2[n][j']: g<2 ? cos(2*pi*k2*n/256) : -sin(...)   (k2 = 2m+(g&1))
// A2[i'][n]: h<2 ? cos(2*pi*k1*n/256) : +sin(...)   (k1 = 2m+(h&1))
// ---------------------------------------------------------------------------
__global__ void k_init() {
    int idx = blockIdx.x * 256 + threadIdx.x;   // 0 .. 16383
    if (idx < 8192) {
        int n = idx >> 6, j = idx & 63;
        int g = j >> 4, m = j & 15;
        int k = 2*m + (g & 1);
        int p = (k * n) & 255;
        float s, c;
        sincospif((float)p * (1.0f/128.0f), &s, &c);
        g_Bm2[idx] = (g < 2) ? c : -s;
    } else {
        int t = idx - 8192;
        int ip = t >> 7, n = t & 127;
        int h = ip >> 4, m = ip & 15;
        int k = 2*m + (h & 1);
        int p = (k * n) & 255;
        float s, c;
        sincospif((float)p * (1.0f/128.0f), &s, &c);
        g_Am2[t] = (h < 2) ? c : s;
    }
}

// ---------------------------------------------------------------------------
// K1: stage-1 folded GEMM  Y'[131072 x 64] = fold(X) @ B2[128 x 64]
// E[n]=x[n]+x[n+128] (even k2), O[n]=x[n]-x[n+128] (odd k2).
// block: 256 thr, tile 128 rows x 64 cols, folded K=128 in 4 chunks of 32,
// per-thread 8x4.  grid: (1024, 2)  y: 0=prediction, 1=ground_truth
// ---------------------------------------------------------------------------
__global__ __launch_bounds__(256) void k_dft1(const float* __restrict__ Xp,
                                              const float* __restrict__ Xg) {
    __shared__ __align__(16) float Es[32][132];
    __shared__ __align__(16) float Os[32][132];
    __shared__ __align__(16) float Bs[32][68];
    const float* X = (blockIdx.y == 0) ? Xp : Xg;
    float* Y = g_Y[blockIdx.y];
    const int R0 = blockIdx.x * 128;
    const int tid = threadIdx.x;
    const int ty = tid >> 4, tx = tid & 15;

    float acc[8][4];
    #pragma unroll
    for (int i = 0; i < 8; i++)
        #pragma unroll
        for (int j = 0; j < 4; j++) acc[i][j] = 0.f;

    for (int c = 0; c < 4; c++) {
        const int col0 = 32 * c;
        #pragma unroll
        for (int u = 0; u < 4; u++) {
            int v = tid + u*256;            // 1024 slots: r 0..127, q 0..7
            int r = v >> 3, q = v & 7;
            const float* row = X + (size_t)(R0 + r)*256 + col0 + 4*q;
            float4 a = *reinterpret_cast<const float4*>(row);
            float4 b = *reinterpret_cast<const float4*>(row + 128);
            Es[4*q+0][r] = a.x + b.x;  Os[4*q+0][r] = a.x - b.x;
            Es[4*q+1][r] = a.y + b.y;  Os[4*q+1][r] = a.y - b.y;
            Es[4*q+2][r] = a.z + b.z;  Os[4*q+2][r] = a.z - b.z;
            Es[4*q+3][r] = a.w + b.w;  Os[4*q+3][r] = a.w - b.w;
        }
        #pragma unroll
        for (int u = 0; u < 2; u++) {
            int v = tid + u*256;
            int k = v >> 4, j4 = v & 15;
            *reinterpret_cast<float4*>(&Bs[k][4*j4]) =
                *reinterpret_cast<const float4*>(g_Bm2 + (size_t)(col0 + k)*64 + 4*j4);
        }
        __syncthreads();
        const float* F = (tx & 4) ? &Os[0][0] : &Es[0][0];  // column parity selects operand
        #pragma unroll 4
        for (int k = 0; k < 32; k++) {
            float4 a0 = *reinterpret_cast<const float4*>(F + k*132 + ty*8);
            float4 a1 = *reinterpret_cast<const float4*>(F + k*132 + ty*8 + 4);
            float4 bv = *reinterpret_cast<const float4*>(&Bs[k][tx*4]);
            float a[8] = {a0.x, a0.y, a0.z, a0.w, a1.x, a1.y, a1.z, a1.w};
            float b[4] = {bv.x, bv.y, bv.z, bv.w};
            #pragma unroll
            for (int i = 0; i < 8; i++)
                #pragma unroll
                for (int j = 0; j < 4; j++)
                    acc[i][j] = fmaf(a[i], b[j], acc[i][j]);
        }
        __syncthreads();
    }
    #pragma unroll
    for (int i = 0; i < 8; i++) {
        float4 o = make_float4(acc[i][0], acc[i][1], acc[i][2], acc[i][3]);
        *reinterpret_cast<float4*>(Y + (size_t)(R0 + ty*8 + i)*64 + tx*4) = o;
    }
}

// ---------------------------------------------------------------------------
// K2: stage-2 folded per (b,c):  P[64x64] = A2[64x128] @ fold(Y)[128x64]
// Row layout i': h=i'>>4 (0=CosE,1=CosO,2=SinE,3=SinO), m=i'&15, k1=2m+(h&1).
// epilogue un-permutes, writes modes/energies/errors/total energy.
// grid 512 blocks x 256 thr, per-thread 4x4 (x2 tensors)
// ---------------------------------------------------------------------------
__global__ __launch_bounds__(256) void k_stage2(float* __restrict__ out) {
    __shared__ __align__(16) float buf[5*2176];   // operands: As,Ep,Op,Eg,Og [32][68] each
    __shared__ float red[8];                       // union with Pp,Pg [64][68] each
    float* As = buf;
    float* Ep = buf + 2176;
    float* Op = buf + 2*2176;
    float* Eg = buf + 3*2176;
    float* Og = buf + 4*2176;
    float* Pp = buf;
    float* Pg = buf + 4352;

    const int bc  = blockIdx.x;
    const int tid = threadIdx.x;
    const int ty = tid >> 4, tx = tid & 15;
    const float* Yp = g_Y[0] + (size_t)bc*256*64;
    const float* Yg = g_Y[1] + (size_t)bc*256*64;

    float ap[4][4], ag[4][4];
    #pragma unroll
    for (int i = 0; i < 4; i++)
        #pragma unroll
        for (int j = 0; j < 4; j++) { ap[i][j] = 0.f; ag[i][j] = 0.f; }

    for (int c = 0; c < 4; c++) {
        const int n0 = 32 * c;
        #pragma unroll
        for (int u = 0; u < 2; u++) {   // As[n][i'] = A2[i'][n0+n] (transpose load)
            int v = tid + u*256;
            int ii = v >> 3, c4 = v & 7;
            float4 av = *reinterpret_cast<const float4*>(g_Am2 + (size_t)ii*128 + n0 + 4*c4);
            As[(4*c4+0)*68 + ii] = av.x;
            As[(4*c4+1)*68 + ii] = av.y;
            As[(4*c4+2)*68 + ii] = av.z;
            As[(4*c4+3)*68 + ii] = av.w;
        }
        #pragma unroll
        for (int u = 0; u < 2; u++) {   // fold pred Y
            int v = tid + u*256;
            int k = v >> 4, j4 = v & 15;
            float4 a = *reinterpret_cast<const float4*>(Yp + (size_t)(n0 + k)*64 + 4*j4);
            float4 b = *reinterpret_cast<const float4*>(Yp + (size_t)(n0 + 128 + k)*64 + 4*j4);
            *reinterpret_cast<float4*>(Ep + k*68 + 4*j4) =
                make_float4(a.x+b.x, a.y+b.y, a.z+b.z, a.w+b.w);
            *reinterpret_cast<float4*>(Op + k*68 + 4*j4) =
                make_float4(a.x-b.x, a.y-b.y, a.z-b.z, a.w-b.w);
        }
        #pragma unroll
        for (int u = 0; u < 2; u++) {   // fold gt Y
            int v = tid + u*256;
            int k = v >> 4, j4 = v & 15;
            float4 a = *reinterpret_cast<const float4*>(Yg + (size_t)(n0 + k)*64 + 4*j4);
            float4 b = *reinterpret_cast<const float4*>(Yg + (size_t)(n0 + 128 + k)*64 + 4*j4);
            *reinterpret_cast<float4*>(Eg + k*68 + 4*j4) =
                make_float4(a.x+b.x, a.y+b.y, a.z+b.z, a.w+b.w);
            *reinterpret_cast<float4*>(Og + k*68 + 4*j4) =
                make_float4(a.x-b.x, a.y-b.y, a.z-b.z, a.w-b.w);
        }
        __syncthreads();
        const float* BP = (ty & 4) ? Op : Ep;   // row-group parity selects operand
        const float* BG = (ty & 4) ? Og : Eg;
        #pragma unroll 4
        for (int k = 0; k < 32; k++) {
            float4 av = *reinterpret_cast<const float4*>(As + k*68 + ty*4);
            float4 bp = *reinterpret_cast<const float4*>(BP + k*68 + tx*4);
            float4 bg = *reinterpret_cast<const float4*>(BG + k*68 + tx*4);
            float a[4]  = {av.x, av.y, av.z, av.w};
            float vp[4] = {bp.x, bp.y, bp.z, bp.w};
            float vg[4] = {bg.x, bg.y, bg.z, bg.w};
            #pragma unroll
            for (int i = 0; i < 4; i++)
                #pragma unroll
                for (int j = 0; j < 4; j++) {
                    ap[i][j] = fmaf(a[i], vp[j], ap[i][j]);
                    ag[i][j] = fmaf(a[i], vg[j], ag[i][j]);
                }
        }
        __syncthreads();
    }
    #pragma unroll
    for (int i = 0; i < 4; i++) {
        *reinterpret_cast<float4*>(&Pp[(ty*4+i)*68 + tx*4]) =
            make_float4(ap[i][0], ap[i][1], ap[i][2], ap[i][3]);
        *reinterpret_cast<float4*>(&Pg[(ty*4+i)*68 + tx*4]) =
            make_float4(ag[i][0], ag[i][1], ag[i][2], ag[i][3]);
    }
    __syncthreads();

    float esum = 0.f;
    #pragma unroll
    for (int u = 0; u < 4; u++) {
        int p  = u*256 + tid;
        int k1 = p >> 5, k2 = p & 31;
        int rc = ((k1 & 1) << 4) | (k1 >> 1);   // permuted row of cos block
        int cc = ((k2 & 1) << 4) | (k2 >> 1);   // permuted col of Re block
        float rp = Pp[rc*68 + cc]      + Pp[(32+rc)*68 + 32 + cc];
        float ip = Pp[rc*68 + 32 + cc] - Pp[(32+rc)*68 + cc];
        float rg = Pg[rc*68 + cc]      + Pg[(32+rc)*68 + 32 + cc];
        float ig = Pg[rc*68 + 32 + cc] - Pg[(32+rc)*68 + cc];
        float en = rp*rp + ip*ip;
        float dr = rp - rg, di = ip - ig;
        size_t gi = (size_t)bc*1024 + p;
        out[OFF_E   + gi] = en;
        out[OFF_ERR + gi] = dr*dr + di*di;
        g_modes[gi] = make_float2(rp, ip);
        esum += en;
    }
    #pragma unroll
    for (int o = 16; o > 0; o >>= 1) esum += __shfl_down_sync(0xffffffffu, esum, o);
    if ((tid & 31) == 0) red[tid >> 5] = esum;
    __syncthreads();
    if (tid == 0) {
        float s = 0.f;
        #pragma unroll
        for (int w = 0; w < 8; w++) s += red[w];
        g_totE[bc] = s;
    }
}

// ---------------------------------------------------------------------------
// K3: MLP per mode point: 2 -> 64 (relu) -> 32 (relu) -> 1 (softplus)
// float4 shared loads, layer-3 folded into layer-2 via shfl reduction,
// energy-fraction + weighted-importance fused into epilogue.
// block: 128 thr, 64 points
// ---------------------------------------------------------------------------
__global__ __launch_bounds__(128) void k_mlp(const float* __restrict__ W1,
                                             const float* __restrict__ b1,
                                             const float* __restrict__ W2,
                                             const float* __restrict__ b2,
                                             const float* __restrict__ W3,
                                             const float* __restrict__ b3v,
                                             float* __restrict__ out) {
    __shared__ __align__(16) float  W1s[2][64];
    __shared__ __align__(16) float  b1s[64];
    __shared__ __align__(16) float  W2s[64][36];
    __shared__ __align__(16) float  b2s[32];
    __shared__ __align__(16) float  W3s[32];
    __shared__ __align__(16) float2 Pts[64];
    __shared__ __align__(16) float  H1t[64][68];   // transposed: H1t[k][p]
    __shared__ float  b3s;

    const int tid  = threadIdx.x;
    const int base = blockIdx.x * 64;

    if (tid < 64) { W1s[0][tid] = W1[tid]; W1s[1][tid] = W1[64 + tid]; b1s[tid] = b1[tid]; }
    for (int v = tid; v < 2048; v += 128) W2s[v >> 5][v & 31] = W2[v];
    if (tid < 32) { b2s[tid] = b2[tid]; W3s[tid] = W3[tid]; }
    if (tid == 0) b3s = b3v[0];
    if (tid < 64) Pts[tid] = g_modes[base + tid];
    __syncthreads();

    { // layer 1: each thread does half a point's 64 outputs
        int p = tid >> 1, jb = (tid & 1) * 32;
        float2 x = Pts[p];
        #pragma unroll 8
        for (int j = 0; j < 32; j++) {
            int jj = jb + j;
            float h = fmaf(x.x, W1s[0][jj], fmaf(x.y, W1s[1][jj], b1s[jj]));
            H1t[jj][p] = fmaxf(h, 0.f);
        }
    }
    __syncthreads();

    { // layer 2 GEMM [64 pts x 32], K=64, per-thread 4x4, layer 3 fused
        int ty = tid >> 3, tx = tid & 7;
        float4 w3 = *reinterpret_cast<const float4*>(&W3s[tx*4]);
        float acc[4][4];
        #pragma unroll
        for (int i = 0; i < 4; i++)
            #pragma unroll
            for (int j = 0; j < 4; j++) acc[i][j] = b2s[tx*4 + j];
        #pragma unroll 8
        for (int k = 0; k < 64; k++) {
            float4 av = *reinterpret_cast<const float4*>(&H1t[k][ty*4]);
            float4 bv = *reinterpret_cast<const float4*>(&W2s[k][tx*4]);
            float a[4] = {av.x, av.y, av.z, av.w};
            float b[4] = {bv.x, bv.y, bv.z, bv.w};
            #pragma unroll
            for (int i = 0; i < 4; i++)
                #pragma unroll
                for (int j = 0; j < 4; j++) acc[i][j] = fmaf(a[i], b[j], acc[i][j]);
        }
        float part[4];
        #pragma unroll
        for (int i = 0; i < 4; i++) {
            part[i] = fmaxf(acc[i][0], 0.f) * w3.x;
            part[i] = fmaf(fmaxf(acc[i][1], 0.f), w3.y, part[i]);
            part[i] = fmaf(fmaxf(acc[i][2], 0.f), w3.z, part[i]);
            part[i] = fmaf(fmaxf(acc[i][3], 0.f), w3.w, part[i]);
        }
        #pragma unroll
        for (int o = 1; o < 8; o <<= 1)
            #pragma unroll
            for (int i = 0; i < 4; i++)
                part[i] += __shfl_xor_sync(0xffffffffu, part[i], o);
        if (tx == 0) {
            int p0 = ty * 4;
            float tot = g_totE[blockIdx.x >> 4] + 1e-8f;
            float4 ev = *reinterpret_cast<const float4*>(&out[OFF_E + base + p0]);
            float uv[4], e[4] = {ev.x, ev.y, ev.z, ev.w};
            float4 uo, fo, wo;
            #pragma unroll
            for (int i = 0; i < 4; i++) {
                float z = part[i] + b3s;
                uv[i] = fmaxf(z, 0.f) + log1pf(expf(-fabsf(z)));   // softplus
            }
            uo = make_float4(uv[0], uv[1], uv[2], uv[3]);
            float f0 = e[0]/tot, f1 = e[1]/tot, f2 = e[2]/tot, f3 = e[3]/tot;
            fo = make_float4(f0, f1, f2, f3);
            wo = make_float4(f0*uv[0], f1*uv[1], f2*uv[2], f3*uv[3]);
            *reinterpret_cast<float4*>(&out[OFF_U  + base + p0]) = uo;
            *reinterpret_cast<float4*>(&out[OFF_EF + base + p0]) = fo;
            *reinterpret_cast<float4*>(&out[OFF_WI + base + p0]) = wo;
        }
    }
}

// ---------------------------------------------------------------------------
// K4: spectra means + Pearson calibration over the 512-sample batch axis.
// grid 32 x 256 thr: 32 modes/block, 8 row-groups of 64 rows each, smem reduce.
// ---------------------------------------------------------------------------
__global__ __launch_bounds__(256) void k_stats(float* __restrict__ out) {
    __shared__ float red[8][96];
    const int tid = threadIdx.x;
    const int g = tid >> 5, lm = tid & 31;
    const int m = blockIdx.x * 32 + lm;
    const float* U  = out + OFF_U;
    const float* E  = out + OFF_E;
    const float* ER = out + OFF_ERR;
    const int r0 = g * 64;

    float su = 0.f, se = 0.f, sr = 0.f;
    #pragma unroll 4
    for (int rr = 0; rr < 64; rr++) {
        int r = r0 + rr;
        su += U [r*1024 + m];
        se += E [r*1024 + m];
        sr += ER[r*1024 + m];
    }
    red[g][lm] = su; red[g][32+lm] = se; red[g][64+lm] = sr;
    __syncthreads();
    if (g == 0) {
        #pragma unroll
        for (int w = 1; w < 8; w++) {
            su += red[w][lm]; se += red[w][32+lm]; sr += red[w][64+lm];
        }
        float mu = su * (1.f/512.f), mr = sr * (1.f/512.f);
        out[OFF_US + m] = mu;
        out[OFF_ES + m] = se * (1.f/512.f);
        red[0][lm] = mu; red[0][32+lm] = mr;
    }
    __syncthreads();
    float mu = red[0][lm], mr = red[0][32+lm];
    __syncthreads();

    float num = 0.f, du = 0.f, de = 0.f;
    #pragma unroll 4
    for (int rr = 0; rr < 64; rr++) {
        int r = r0 + rr;
        float uc = U [r*1024 + m] - mu;
        float ec = ER[r*1024 + m] - mr;
        num += uc*ec; du += uc*uc; de += ec*ec;
    }
    red[g][lm] = num; red[g][32+lm] = du; red[g][64+lm] = de;
    __syncthreads();
    if (g == 0) {
        #pragma unroll
        for (int w = 1; w < 8; w++) {
            num += red[w][lm]; du += red[w][32+lm]; de += red[w][64+lm];
        }
        out[OFF_CAL + m] = num / (sqrtf(du * de) + 1e-8f);
    }
}

// ---------------------------------------------------------------------------
extern "C" void kernel_launch(void* const* d_in, const int* in_sizes, int n_in,
                              void* d_out, int out_size) {
    const float* pred = (const float*)d_in[0];
    // d_in[1] (uncertainty) is unused by the reference math
    const float* gt   = (const float*)d_in[2];
    const float* W1   = (const float*)d_in[3];
    const float* b1   = (const float*)d_in[4];
    const float* W2   = (const float*)d_in[5];
    const float* b2   = (const float*)d_in[6];
    const float* W3   = (const float*)d_in[7];
    const float* b3   = (const float*)d_in[8];
    float* out = (float*)d_out;

    k_init  <<<64, 256>>>();
    k_dft1  <<<dim3(1024, 2), 256>>>(pred, gt);
    k_stage2<<<512, 256>>>(out);
    k_mlp   <<<NMODE/64, 128>>>(W1, b1, W2, b2, W3, b3, out);
    k_stats <<<32, 256>>>(out);
}